// round 2
// baseline (speedup 1.0000x reference)
#include <cuda_runtime.h>
#include <cuda_bf16.h>
#include <cstdint>

// Problem constants
#define BATCH 8
#define SLEN  2048
#define DIM   256
#define KTOT  1280            // 4 relations + root, each DIM rows
#define MROWS (BATCH * SLEN)  // 16384

// Scratch (device globals; no dynamic allocation allowed)
__device__ float g_W[KTOT * DIM];        // stacked [W0;W1;W2;W3;root], row-major [k][o]
__device__ float g_total[BATCH * DIM];   // per-batch column sums of x
__device__ float g_U[(size_t)MROWS * KTOT]; // aggregated inputs, 84 MB

// ---------------------------------------------------------------------------
// Kernel 1: W_r = comp[r,0]*basis[0] + comp[r,1]*basis[1]; row 1024.. = root
// grid: KTOT blocks, DIM threads
__global__ void build_w_kernel(const float* __restrict__ comp,
                               const float* __restrict__ basis,
                               const float* __restrict__ root) {
    int k = blockIdx.x;      // 0..1279
    int o = threadIdx.x;     // 0..255
    int r = k >> 8;
    int i = k & 255;
    float v;
    if (r < 4) {
        v = comp[r * 2 + 0] * basis[0 * DIM * DIM + i * DIM + o]
          + comp[r * 2 + 1] * basis[1 * DIM * DIM + i * DIM + o];
    } else {
        v = root[i * DIM + o];
    }
    g_W[(size_t)k * DIM + o] = v;
}

// ---------------------------------------------------------------------------
// Kernel 2: g_total[b][i] = sum_s x[b][s][i]
// grid: BATCH blocks, DIM threads
__global__ void build_total_kernel(const float* __restrict__ x) {
    int b = blockIdx.x;
    int i = threadIdx.x;
    const float* p = x + (size_t)b * SLEN * DIM + i;
    float s0 = 0.f, s1 = 0.f, s2 = 0.f, s3 = 0.f;
    #pragma unroll 4
    for (int t = 0; t < SLEN; t += 4) {
        s0 += p[(size_t)(t + 0) * DIM];
        s1 += p[(size_t)(t + 1) * DIM];
        s2 += p[(size_t)(t + 2) * DIM];
        s3 += p[(size_t)(t + 3) * DIM];
    }
    g_total[b * DIM + i] = (s0 + s1) + (s2 + s3);
}

// ---------------------------------------------------------------------------
// Kernel 3: build aggregated input U[row = b*S+t][k], k = r*256+i
//   r=0: x[t+1] (or 0)
//   r=1: mean{x[t], x[t+2]}
//   r=2: mean{x[t-1], x[t+3]}
//   r=3: (total - window_sum)/deg3,  window = [t-1, t+3] ∩ [0,S)
//   r=4: x[t]  (root term)
// grid: MROWS blocks, DIM threads
__global__ void build_u_kernel(const float* __restrict__ x) {
    int row = blockIdx.x;
    int b = row / SLEN;
    int t = row % SLEN;
    int i = threadIdx.x;
    const float* xb = x + (size_t)b * SLEN * DIM;

    float xm1 = (t >= 1)       ? xb[(size_t)(t - 1) * DIM + i] : 0.f;
    float x0  =                  xb[(size_t)(t    ) * DIM + i];
    float xp1 = (t + 1 < SLEN) ? xb[(size_t)(t + 1) * DIM + i] : 0.f;
    float xp2 = (t + 2 < SLEN) ? xb[(size_t)(t + 2) * DIM + i] : 0.f;
    float xp3 = (t + 3 < SLEN) ? xb[(size_t)(t + 3) * DIM + i] : 0.f;

    // r=0: single source s=t+1 (deg 1 or 0)
    float u0 = xp1;
    // r=1: sources {t, t+2}
    int c1 = 1 + (t + 2 < SLEN);
    float u1 = (x0 + xp2) / (float)c1;
    // r=2: sources {t-1, t+3}
    int c2 = (t >= 1) + (t + 3 < SLEN);
    float u2 = (c2 > 0) ? (xm1 + xp3) / (float)c2 : 0.f;
    // r=3: complement of window [t-1, t+3]
    int cwin = 1 + (t >= 1) + (t + 1 < SLEN) + (t + 2 < SLEN) + (t + 3 < SLEN);
    int c3 = SLEN - cwin;
    float u3 = (g_total[b * DIM + i] - (xm1 + x0 + xp1 + xp2 + xp3)) / (float)c3;

    float* Urow = g_U + (size_t)row * KTOT;
    Urow[0 * DIM + i] = u0;
    Urow[1 * DIM + i] = u1;
    Urow[2 * DIM + i] = u2;
    Urow[3 * DIM + i] = u3;
    Urow[4 * DIM + i] = x0;
}

// ---------------------------------------------------------------------------
// Kernel 4: out[M, 256] = U[M, 1280] @ W[1280, 256] + bias
// Tiled SGEMM: 64x64 block tile, BK=16, 256 threads, 4x4 per-thread micro-tile
#define BM 64
#define BN 64
#define BK 16

__global__ __launch_bounds__(256)
void gemm_kernel(const float* __restrict__ bias, float* __restrict__ out) {
    __shared__ float As[BK][BM];      // transposed A tile
    __shared__ float Bs[BK][BN];

    int bm = blockIdx.x;              // 0..255 (M tiles)
    int bn = blockIdx.y;              // 0..3   (N tiles)
    int tid = threadIdx.x;
    int tx = tid & 15;                // 0..15 -> 4 cols each
    int ty = tid >> 4;                // 0..15 -> 4 rows each

    const float* Ublk = g_U + (size_t)(bm * BM) * KTOT;
    const float* Wblk = g_W + bn * BN;

    float acc[4][4];
    #pragma unroll
    for (int a = 0; a < 4; a++)
        #pragma unroll
        for (int c = 0; c < 4; c++) acc[a][c] = 0.f;

    // loader indices
    int ar = tid >> 2;                // 0..63 row in A tile
    int ak = (tid & 3) * 4;           // 0,4,8,12 k-offset (float4)
    int br = tid >> 4;                // 0..15 k row in B tile
    int bc = (tid & 15) * 4;          // 0..60 col (float4)

    for (int k0 = 0; k0 < KTOT; k0 += BK) {
        float4 av = *(const float4*)(Ublk + (size_t)ar * KTOT + k0 + ak);
        float4 bv = *(const float4*)(Wblk + (size_t)(k0 + br) * DIM + bc);

        As[ak + 0][ar] = av.x;
        As[ak + 1][ar] = av.y;
        As[ak + 2][ar] = av.z;
        As[ak + 3][ar] = av.w;
        *(float4*)&Bs[br][bc] = bv;
        __syncthreads();

        #pragma unroll
        for (int kk = 0; kk < BK; kk++) {
            float4 a = *(const float4*)&As[kk][ty * 4];
            float4 b = *(const float4*)&Bs[kk][tx * 4];
            float ax[4] = {a.x, a.y, a.z, a.w};
            float bxv[4] = {b.x, b.y, b.z, b.w};
            #pragma unroll
            for (int mi = 0; mi < 4; mi++)
                #pragma unroll
                for (int ni = 0; ni < 4; ni++)
                    acc[mi][ni] = fmaf(ax[mi], bxv[ni], acc[mi][ni]);
        }
        __syncthreads();
    }

    // epilogue: add bias, store
    int col0 = bn * BN + tx * 4;
    float4 bb = *(const float4*)(bias + col0);
    float badd[4] = {bb.x, bb.y, bb.z, bb.w};
    #pragma unroll
    for (int mi = 0; mi < 4; mi++) {
        int row = bm * BM + ty * 4 + mi;
        float4 v;
        v.x = acc[mi][0] + badd[0];
        v.y = acc[mi][1] + badd[1];
        v.z = acc[mi][2] + badd[2];
        v.w = acc[mi][3] + badd[3];
        *(float4*)(out + (size_t)row * DIM + col0) = v;
    }
}

// ---------------------------------------------------------------------------
extern "C" void kernel_launch(void* const* d_in, const int* in_sizes, int n_in,
                              void* d_out, int out_size) {
    const float* x     = (const float*)d_in[0];  // [8, 2048, 256]
    const float* comp  = (const float*)d_in[1];  // [4, 2]
    const float* basis = (const float*)d_in[2];  // [2, 256, 256]
    const float* root  = (const float*)d_in[3];  // [256, 256]
    const float* bias  = (const float*)d_in[4];  // [256]
    float* out = (float*)d_out;                  // [8, 2048, 256]

    build_w_kernel<<<KTOT, DIM>>>(comp, basis, root);
    build_total_kernel<<<BATCH, DIM>>>(x);
    build_u_kernel<<<MROWS, DIM>>>(x);
    dim3 grid(MROWS / BM, DIM / BN);
    gemm_kernel<<<grid, 256>>>(bias, out);
}

// round 6
// speedup vs baseline: 3.0021x; 3.0021x over previous
#include <cuda_runtime.h>
#include <cuda_bf16.h>
#include <cstdint>

// Problem constants
#define BATCH 8
#define SLEN  2048
#define DIM   256
#define KTOT  1280            // 4 relations + root, each DIM k-rows
#define MROWS (BATCH * SLEN)  // 16384

// ---------------------------------------------------------------------------
// Device scratch (no dynamic allocation allowed)
__device__ __nv_bfloat16 g_Ah[(size_t)MROWS * KTOT];  // 42 MB
__device__ __nv_bfloat16 g_Al[(size_t)MROWS * KTOT];  // 42 MB
__device__ __nv_bfloat16 g_Bh[(size_t)DIM * KTOT];    // W^T [n][k] hi
__device__ __nv_bfloat16 g_Bl[(size_t)DIM * KTOT];    // W^T [n][k] lo
__device__ float g_total[BATCH * DIM];

// ---------------------------------------------------------------------------
__device__ __forceinline__ uint32_t smem_u32(const void* p) {
    return (uint32_t)__cvta_generic_to_shared(p);
}
#define SWZ(o) ((o) ^ (((o) >> 3) & 0x70))

#define CP_ASYNC16(saddr, gptr) \
    asm volatile("cp.async.cg.shared.global [%0], [%1], 16;" \
                 :: "r"(saddr), "l"(gptr))
#define CP_COMMIT() asm volatile("cp.async.commit_group;" ::: "memory")
#define CP_WAIT1()  asm volatile("cp.async.wait_group 1;" ::: "memory")
#define CP_WAIT0()  asm volatile("cp.async.wait_group 0;" ::: "memory")

#define LDSM_X4(R, addr) \
    asm volatile("ldmatrix.sync.aligned.m8n8.x4.shared.b16 {%0,%1,%2,%3}, [%4];" \
                 : "=r"((R)[0]), "=r"((R)[1]), "=r"((R)[2]), "=r"((R)[3]) \
                 : "r"(addr))

#define MMA16816(D, A, B0, B1) \
    asm volatile("mma.sync.aligned.m16n8k16.row.col.f32.bf16.bf16.f32 " \
                 "{%0,%1,%2,%3}, {%4,%5,%6,%7}, {%8,%9}, {%0,%1,%2,%3};" \
                 : "+f"((D)[0]), "+f"((D)[1]), "+f"((D)[2]), "+f"((D)[3]) \
                 : "r"((A)[0]), "r"((A)[1]), "r"((A)[2]), "r"((A)[3]), \
                   "r"(B0), "r"(B1))

// ---------------------------------------------------------------------------
// Kernel 1: build stacked W^T in bf16 hi/lo.  k = r*256 + i; row o of W^T.
__global__ void build_w_kernel(const float* __restrict__ comp,
                               const float* __restrict__ basis,
                               const float* __restrict__ root) {
    int o = blockIdx.x;
    int tid = threadIdx.x;
    #pragma unroll
    for (int kk = 0; kk < 5; kk++) {
        int i = tid;
        float v;
        if (kk < 4) {
            v = comp[kk * 2 + 0] * basis[(size_t)i * DIM + o]
              + comp[kk * 2 + 1] * basis[(size_t)DIM * DIM + (size_t)i * DIM + o];
        } else {
            v = root[(size_t)i * DIM + o];
        }
        int k = kk * 256 + tid;
        __nv_bfloat16 hi = __float2bfloat16(v);
        float lo = v - __bfloat162float(hi);
        g_Bh[(size_t)o * KTOT + k] = hi;
        g_Bl[(size_t)o * KTOT + k] = __float2bfloat16(lo);
    }
}

// ---------------------------------------------------------------------------
// Kernel 2a/2b: per-batch column totals (parallel: 32 segments per batch)
__global__ void zero_total_kernel() {
    g_total[blockIdx.x * DIM + threadIdx.x] = 0.f;
}
__global__ void partial_total_kernel(const float* __restrict__ x) {
    int b = blockIdx.x >> 5;
    int seg = blockIdx.x & 31;
    int i = threadIdx.x;
    const float* p = x + ((size_t)b * SLEN + seg * 64) * DIM + i;
    float s0 = 0.f, s1 = 0.f;
    #pragma unroll 8
    for (int t = 0; t < 64; t += 2) {
        s0 += p[(size_t)t * DIM];
        s1 += p[(size_t)(t + 1) * DIM];
    }
    atomicAdd(&g_total[b * DIM + i], s0 + s1);
}

// ---------------------------------------------------------------------------
// Kernel 3: build A rows (bf16 hi/lo split of aggregated inputs)
__device__ __forceinline__ void split_store(float v, size_t idx) {
    __nv_bfloat16 hi = __float2bfloat16(v);
    float lo = v - __bfloat162float(hi);
    g_Ah[idx] = hi;
    g_Al[idx] = __float2bfloat16(lo);
}

__global__ void build_a_kernel(const float* __restrict__ x) {
    int row = blockIdx.x;
    int b = row >> 11;
    int t = row & 2047;
    int i = threadIdx.x;
    const float* xb = x + (size_t)b * SLEN * DIM;

    float xm1 = (t >= 1)        ? xb[(size_t)(t - 1) * DIM + i] : 0.f;
    float x0  =                   xb[(size_t)(t    ) * DIM + i];
    float xp1 = (t + 1 < SLEN)  ? xb[(size_t)(t + 1) * DIM + i] : 0.f;
    float xp2 = (t + 2 < SLEN)  ? xb[(size_t)(t + 2) * DIM + i] : 0.f;
    float xp3 = (t + 3 < SLEN)  ? xb[(size_t)(t + 3) * DIM + i] : 0.f;

    float u0 = xp1;                                         // r=0: {t+1}
    int c1 = 1 + (t + 2 < SLEN);
    float u1 = (x0 + xp2) / (float)c1;                      // r=1: {t, t+2}
    int c2 = (t >= 1) + (t + 3 < SLEN);
    float u2 = (c2 > 0) ? (xm1 + xp3) / (float)c2 : 0.f;    // r=2: {t-1, t+3}
    int cwin = 1 + (t >= 1) + (t + 1 < SLEN) + (t + 2 < SLEN) + (t + 3 < SLEN);
    int c3 = SLEN - cwin;
    float u3 = (g_total[b * DIM + i] - (xm1 + x0 + xp1 + xp2 + xp3)) / (float)c3;

    size_t base = (size_t)row * KTOT + i;
    split_store(u0, base + 0 * DIM);
    split_store(u1, base + 1 * DIM);
    split_store(u2, base + 2 * DIM);
    split_store(u3, base + 3 * DIM);
    split_store(x0, base + 4 * DIM);
}

// ---------------------------------------------------------------------------
// Kernel 4: HMMA (mma.sync bf16) GEMM.  out[16384,256] = A[.,1280] @ W^T + bias
// bf16x3 split: D += Ah*Bh + Ah*Bl + Al*Bh.
// CTA tile 128x128, K-chunk 64, double-buffered cp.async, 8 warps (64x32 each).
#define BM 128
#define BN 128
#define KC 64
#define NCHUNK (KTOT / KC)          // 20
#define TILE_BYTES 16384            // 128 rows * 128 B
#define STAGE_BYTES (4 * TILE_BYTES)  // Ah, Al, Bh, Bl
#define SMEM_BYTES (2 * STAGE_BYTES)  // 131072
#define KROWB (KTOT * 2)            // 2560 bytes per K-row

__global__ __launch_bounds__(256, 1)
void hmma_kernel(const float* __restrict__ bias, float* __restrict__ out) {
    extern __shared__ char smem[];
    const int tid = threadIdx.x;
    const int wid = tid >> 5;
    const int lane = tid & 31;
    const int warp_m = wid & 1;   // 2 warps in M
    const int warp_n = wid >> 1;  // 4 warps in N
    const int m0 = blockIdx.x * BM;
    const int n0 = blockIdx.y * BN;

    const char* Ah_g = (const char*)g_Ah + (size_t)m0 * KROWB;
    const char* Al_g = (const char*)g_Al + (size_t)m0 * KROWB;
    const char* Bh_g = (const char*)g_Bh + (size_t)n0 * KROWB;
    const char* Bl_g = (const char*)g_Bl + (size_t)n0 * KROWB;

    // loader: each thread covers 4 (row, 16B-slot) pairs per 16KB tile
    const int lr = tid >> 3;            // base row 0..31 (stride 32)
    const int lq = (tid & 7) * 16;      // byte slot in 128B row

    auto load_stage = [&](int c, int s) {
        const int k0b = c * (KC * 2);   // 128-byte chunk offset within K-row
        uint32_t sbase = smem_u32(smem + s * STAGE_BYTES);
        #pragma unroll
        for (int it = 0; it < 4; it++) {
            int r = lr + it * 32;
            size_t goff = (size_t)r * KROWB + k0b + lq;
            uint32_t so = SWZ(r * 128 + lq);
            CP_ASYNC16(sbase + so,                  Ah_g + goff);
            CP_ASYNC16(sbase + TILE_BYTES + so,     Al_g + goff);
            CP_ASYNC16(sbase + 2 * TILE_BYTES + so, Bh_g + goff);
            CP_ASYNC16(sbase + 3 * TILE_BYTES + so, Bl_g + goff);
        }
    };

    float acc[4][4][4];
    #pragma unroll
    for (int mi = 0; mi < 4; mi++)
        #pragma unroll
        for (int e = 0; e < 4; e++)
            #pragma unroll
            for (int r = 0; r < 4; r++) acc[mi][e][r] = 0.f;

    load_stage(0, 0);
    CP_COMMIT();

    // ldmatrix lane addressing (row = low 4 lane bits, 16B half = bit 4)
    const int lrow = lane & 15;
    const int lhalf = (lane >> 4) * 16;

    for (int c = 0; c < NCHUNK; c++) {
        int s = c & 1;
        if (c + 1 < NCHUNK) {
            load_stage(c + 1, s ^ 1);
            CP_COMMIT();
            CP_WAIT1();
        } else {
            CP_WAIT0();
        }
        __syncthreads();

        uint32_t Ab  = smem_u32(smem + s * STAGE_BYTES);
        uint32_t Alb = Ab + TILE_BYTES;
        uint32_t Bb  = Ab + 2 * TILE_BYTES;
        uint32_t Blb = Ab + 3 * TILE_BYTES;

        #pragma unroll
        for (int j = 0; j < 4; j++) {       // 4 k-steps of 16
            uint32_t ah[4][4], al[4][4], bh[2][4], bl[2][4];
            int byte = j * 32 + lhalf;
            #pragma unroll
            for (int mi = 0; mi < 4; mi++) {
                int row = warp_m * 64 + mi * 16 + lrow;
                uint32_t off = SWZ(row * 128 + byte);
                LDSM_X4(ah[mi], Ab + off);
                LDSM_X4(al[mi], Alb + off);
            }
            #pragma unroll
            for (int p = 0; p < 2; p++) {
                int row = warp_n * 32 + p * 16 + lrow;
                uint32_t off = SWZ(row * 128 + byte);
                LDSM_X4(bh[p], Bb + off);
                LDSM_X4(bl[p], Blb + off);
            }
            #pragma unroll
            for (int mi = 0; mi < 4; mi++) {
                #pragma unroll
                for (int e = 0; e < 4; e++) {
                    int p = e >> 1, h = e & 1;
                    MMA16816(acc[mi][e], ah[mi], bh[p][h], bh[p][h + 2]);
                    MMA16816(acc[mi][e], ah[mi], bl[p][h], bl[p][h + 2]);
                    MMA16816(acc[mi][e], al[mi], bh[p][h], bh[p][h + 2]);
                }
            }
        }
        __syncthreads();
    }

    // Epilogue: acc -> +bias -> out
    const int row_base = m0 + warp_m * 64;
    const int col_base = n0 + warp_n * 32;
    const int tr = lane >> 2;
    const int tc = (lane & 3) * 2;
    #pragma unroll
    for (int e = 0; e < 4; e++) {
        int col = col_base + e * 8 + tc;
        float2 bb = *(const float2*)(bias + col);
        #pragma unroll
        for (int mi = 0; mi < 4; mi++) {
            int row = row_base + mi * 16 + tr;
            float2 v0, v1;
            v0.x = acc[mi][e][0] + bb.x;
            v0.y = acc[mi][e][1] + bb.y;
            v1.x = acc[mi][e][2] + bb.x;
            v1.y = acc[mi][e][3] + bb.y;
            *(float2*)(out + (size_t)row * DIM + col) = v0;
            *(float2*)(out + (size_t)(row + 8) * DIM + col) = v1;
        }
    }
}

// ---------------------------------------------------------------------------
extern "C" void kernel_launch(void* const* d_in, const int* in_sizes, int n_in,
                              void* d_out, int out_size) {
    const float* x     = (const float*)d_in[0];  // [8, 2048, 256]
    const float* comp  = (const float*)d_in[1];  // [4, 2]
    const float* basis = (const float*)d_in[2];  // [2, 256, 256]
    const float* root  = (const float*)d_in[3];  // [256, 256]
    const float* bias  = (const float*)d_in[4];  // [256]
    float* out = (float*)d_out;                  // [8, 2048, 256]

    cudaFuncSetAttribute(hmma_kernel, cudaFuncAttributeMaxDynamicSharedMemorySize,
                         SMEM_BYTES);

    build_w_kernel<<<DIM, 256>>>(comp, basis, root);
    zero_total_kernel<<<BATCH, DIM>>>();
    partial_total_kernel<<<BATCH * 32, DIM>>>(x);
    build_a_kernel<<<MROWS, DIM>>>(x);
    dim3 grid(MROWS / BM, DIM / BN);
    hmma_kernel<<<grid, 256, SMEM_BYTES>>>(bias, out);
}